// round 4
// baseline (speedup 1.0000x reference)
#include <cuda_runtime.h>

// GRUAdder: B=1048576, T=4, I=2, H=16
// out = concat(hidden_table[B,4,16], sum_logits[B,4], carry[B,1], output_logits[B,5]) fp32

static constexpr int BATCH   = 1048576;
static constexpr int TT      = 4;
static constexpr int HH      = 16;
static constexpr int NG      = 48;   // 3*H gate rows
static constexpr int KP      = 8;    // H/2 k-pairs
static constexpr int THREADS = 128;

typedef unsigned long long u64;

__device__ __forceinline__ u64 pack2(float lo, float hi) {
    u64 r; asm("mov.b64 %0, {%1, %2};" : "=l"(r) : "f"(lo), "f"(hi)); return r;
}
__device__ __forceinline__ float2 unpack2(u64 v) {
    float2 f; asm("mov.b64 {%0, %1}, %2;" : "=f"(f.x), "=f"(f.y) : "l"(v)); return f;
}
__device__ __forceinline__ void ffma2(u64 &d, u64 a, u64 b) {
    asm("fma.rn.f32x2 %0, %1, %2, %0;" : "+l"(d) : "l"(a), "l"(b));
}
__device__ __forceinline__ float hsum2(u64 v) { float2 f = unpack2(v); return f.x + f.y; }
__device__ __forceinline__ float sigmoid_f(float x) {
    return __fdividef(1.0f, 1.0f + __expf(-x));
}
__device__ __forceinline__ float tanh_f(float x) {
    float e = __expf(2.0f * x);
    return __fdividef(e - 1.0f, e + 1.0f);
}

// One gate pre-activation for ONE batch element. Reads only old h.
template<bool IH, bool HHON>
__device__ __forceinline__ float gate1(const u64* __restrict__ wrow, u64 wih, float bias,
                                       u64 xp, const u64* h2)
{
    u64 a = pack2(bias, 0.0f);
    if (IH) ffma2(a, wih, xp);
    if (HHON) {
#pragma unroll
        for (int kk = 0; kk < KP; ++kk) ffma2(a, wrow[kk], h2[kk]);
    }
    return hsum2(a);
}

__global__ void __launch_bounds__(THREADS, 4)
gru_adder_kernel(const float* __restrict__ x,       // [B,4,2]
                 const float* __restrict__ w_ih,    // [48,2]
                 const float* __restrict__ w_hh,    // [48,16]
                 const float* __restrict__ b_ih,    // [48]
                 const float* __restrict__ b_hh,    // [48]
                 const float* __restrict__ w_sum,   // [16]
                 const float* __restrict__ b_sum,   // [1]
                 const float* __restrict__ w_carry, // [16]
                 const float* __restrict__ b_carry, // [1]
                 float* __restrict__ out,
                 long long off_hid, long long off_sum,
                 long long off_car, long long off_log)
{
    __shared__ u64   s_whh2[NG][KP];  // {w_hh[g][2k], w_hh[g][2k+1]}
    __shared__ u64   s_wih2[NG];      // {w_ih[g][0], w_ih[g][1]}
    __shared__ float s_brz[32];       // b_ih + b_hh for r,z gates
    __shared__ float s_bin[16];       // b_ih[32+j]
    __shared__ float s_bhn[16];       // b_hh[32+j]
    __shared__ u64   s_ws2[KP], s_wc2[KP];
    __shared__ float s_bs, s_bc;

    const int tid = threadIdx.x;
    for (int i = tid; i < NG * KP; i += THREADS) {
        int g = i / KP, kk = i % KP;
        s_whh2[g][kk] = pack2(w_hh[g * HH + 2 * kk], w_hh[g * HH + 2 * kk + 1]);
    }
    if (tid < NG) s_wih2[tid] = pack2(w_ih[tid * 2], w_ih[tid * 2 + 1]);
    if (tid < 32) s_brz[tid] = b_ih[tid] + b_hh[tid];
    if (tid < 16) { s_bin[tid] = b_ih[32 + tid]; s_bhn[tid] = b_hh[32 + tid]; }
    if (tid < KP) {
        s_ws2[tid] = pack2(w_sum[2 * tid], w_sum[2 * tid + 1]);
        s_wc2[tid] = pack2(w_carry[2 * tid], w_carry[2 * tid + 1]);
    }
    if (tid == 0) { s_bs = b_sum[0]; s_bc = b_carry[0]; }
    __syncthreads();

    const int e = blockIdx.x * THREADS + tid;

    const float4* xp4 = reinterpret_cast<const float4*>(x + (size_t)e * (TT * 2));
    float4 x0 = xp4[0], x1 = xp4[1];
    u64 xp[TT] = { pack2(x0.x, x0.y), pack2(x0.z, x0.w),
                   pack2(x1.x, x1.y), pack2(x1.z, x1.w) };

    u64 h2[KP];
#pragma unroll
    for (int kk = 0; kk < KP; ++kk) h2[kk] = 0ull;

#pragma unroll
    for (int t = 0; t < TT; ++t) {
        const u64 xt = xp[t];
        const bool hh_on = (t != 0);   // folds at compile time

        float hn[HH];                  // new h, built while old h stays intact
#pragma unroll
        for (int j = 0; j < HH; ++j) {
            float gr, gz, ni, nh;
            if (hh_on) {
                gr = gate1<true,  true >(s_whh2[j],      s_wih2[j],      s_brz[j],      xt, h2);
                gz = gate1<true,  true >(s_whh2[16 + j], s_wih2[16 + j], s_brz[16 + j], xt, h2);
                ni = gate1<true,  false>(nullptr,        s_wih2[32 + j], s_bin[j],      xt, h2);
                nh = gate1<false, true >(s_whh2[32 + j], 0ull,           s_bhn[j],      xt, h2);
            } else {
                gr = gate1<true,  false>(nullptr, s_wih2[j],      s_brz[j],      xt, h2);
                gz = gate1<true,  false>(nullptr, s_wih2[16 + j], s_brz[16 + j], xt, h2);
                ni = gate1<true,  false>(nullptr, s_wih2[32 + j], s_bin[j],      xt, h2);
                nh = s_bhn[j];
            }
            float r = sigmoid_f(gr);
            float z = sigmoid_f(gz);
            float n = tanh_f(ni + r * nh);
            float ho = (j & 1) ? unpack2(h2[j >> 1]).y : unpack2(h2[j >> 1]).x;
            hn[j] = n + z * (ho - n);
        }
#pragma unroll
        for (int kk = 0; kk < KP; ++kk) h2[kk] = pack2(hn[2 * kk], hn[2 * kk + 1]);

        // sum logit
        u64 sa = pack2(s_bs, 0.0f);
#pragma unroll
        for (int kk = 0; kk < KP; ++kk) ffma2(sa, s_ws2[kk], h2[kk]);
        float sO = hsum2(sa);

        if (off_hid >= 0) {
            float4* po = reinterpret_cast<float4*>(out + off_hid + ((size_t)e * TT + t) * HH);
            po[0] = make_float4(hn[0],  hn[1],  hn[2],  hn[3]);
            po[1] = make_float4(hn[4],  hn[5],  hn[6],  hn[7]);
            po[2] = make_float4(hn[8],  hn[9],  hn[10], hn[11]);
            po[3] = make_float4(hn[12], hn[13], hn[14], hn[15]);
        }
        if (off_sum >= 0) out[off_sum + (size_t)e * TT + t] = sO;
        if (off_log >= 0) out[off_log + (size_t)e * (TT + 1) + t] = sO;
    }

    u64 ca = pack2(s_bc, 0.0f);
#pragma unroll
    for (int kk = 0; kk < KP; ++kk) ffma2(ca, s_wc2[kk], h2[kk]);
    float cO = hsum2(ca);
    if (off_car >= 0) out[off_car + e] = cO;
    if (off_log >= 0) out[off_log + (size_t)e * (TT + 1) + TT] = cO;
}

extern "C" void kernel_launch(void* const* d_in, const int* in_sizes, int n_in,
                              void* d_out, int out_size)
{
    const float* x       = (const float*)d_in[0];
    const float* w_ih    = (const float*)d_in[1];
    const float* w_hh    = (const float*)d_in[2];
    const float* b_ih    = (const float*)d_in[3];
    const float* b_hh    = (const float*)d_in[4];
    const float* w_sum   = (const float*)d_in[5];
    const float* b_sum   = (const float*)d_in[6];
    const float* w_carry = (const float*)d_in[7];
    const float* b_carry = (const float*)d_in[8];
    float* out = (float*)d_out;

    const long long HID = 0;
    const long long SUM = (long long)BATCH * TT * HH;          // 67108864
    const long long CAR = SUM + (long long)BATCH * TT;         // 71303168
    const long long LOG = CAR + (long long)BATCH;              // 72351744
    const long long FULL = LOG + (long long)BATCH * (TT + 1);  // 77594624

    long long oh = -1, os = -1, oc = -1, ol = -1;
    long long sz = (long long)out_size;
    if (sz == FULL)                               { oh = HID; os = SUM; oc = CAR; ol = LOG; }
    else if (sz == (long long)BATCH * TT * HH)    { oh = 0; }
    else if (sz == (long long)BATCH * (TT + 1))   { ol = 0; }
    else if (sz == (long long)BATCH * TT)         { os = 0; }
    else if (sz == (long long)BATCH)              { oc = 0; }
    else                                          { oh = HID; os = SUM; oc = CAR; ol = LOG; }

    const int blocks = BATCH / THREADS;   // 8192
    gru_adder_kernel<<<blocks, THREADS>>>(x, w_ih, w_hh, b_ih, b_hh,
                                          w_sum, b_sum, w_carry, b_carry,
                                          out, oh, os, oc, ol);
}

// round 5
// speedup vs baseline: 6.1329x; 6.1329x over previous
#include <cuda_runtime.h>

// GRUAdder: B=1048576, T=4, I=2, H=16
// out = concat(hidden_table[B,4,16], sum_logits[B,4], carry[B,1], output_logits[B,5]) fp32

static constexpr int BATCH   = 1048576;
static constexpr int TT      = 4;
static constexpr int HH      = 16;
static constexpr int NG      = 48;   // 3*H gate rows
static constexpr int KP      = 8;    // H/2 k-pairs
static constexpr int THREADS = 128;

typedef unsigned long long u64;

__device__ __forceinline__ u64 pack2(float lo, float hi) {
    u64 r; asm("mov.b64 %0, {%1, %2};" : "=l"(r) : "f"(lo), "f"(hi)); return r;
}
__device__ __forceinline__ float2 unpack2(u64 v) {
    float2 f; asm("mov.b64 {%0, %1}, %2;" : "=f"(f.x), "=f"(f.y) : "l"(v)); return f;
}
__device__ __forceinline__ void ffma2(u64 &d, u64 a, u64 b) {
    asm("fma.rn.f32x2 %0, %1, %2, %0;" : "+l"(d) : "l"(a), "l"(b));
}
__device__ __forceinline__ float hsum2(u64 v) { float2 f = unpack2(v); return f.x + f.y; }
__device__ __forceinline__ float sigmoid_f(float x) {
    return __fdividef(1.0f, 1.0f + __expf(-x));
}
__device__ __forceinline__ float tanh_f(float x) {
    float e = __expf(2.0f * x);
    return __fdividef(e - 1.0f, e + 1.0f);
}

__global__ void __launch_bounds__(THREADS, 5)
gru_adder_kernel(const float* __restrict__ x,       // [B,4,2]
                 const float* __restrict__ w_ih,    // [48,2]
                 const float* __restrict__ w_hh,    // [48,16]
                 const float* __restrict__ b_ih,    // [48]
                 const float* __restrict__ b_hh,    // [48]
                 const float* __restrict__ w_sum,   // [16]
                 const float* __restrict__ b_sum,   // [1]
                 const float* __restrict__ w_carry, // [16]
                 const float* __restrict__ b_carry, // [1]
                 float* __restrict__ out,
                 long long off_hid, long long off_sum,
                 long long off_car, long long off_log)
{
    __shared__ u64   s_whh2[NG][KP];   // {w_hh[g][2k], w_hh[g][2k+1]}
    __shared__ u64   s_wih2[NG];       // {w_ih[g][0], w_ih[g][1]}
    __shared__ float s_brz[32];        // b_ih + b_hh for r,z gates
    __shared__ float s_bin[16];        // b_ih[32+j]
    __shared__ float s_bhn[16];        // b_hh[32+j]
    __shared__ u64   s_ws2[KP], s_wc2[KP];
    __shared__ float s_bs, s_bc;
    __shared__ float s_hn[HH][THREADS];  // per-thread new-h staging (transposed, conflict-free)

    const int tid = threadIdx.x;
    for (int i = tid; i < NG * KP; i += THREADS) {
        int g = i / KP, kk = i % KP;
        s_whh2[g][kk] = pack2(w_hh[g * HH + 2 * kk], w_hh[g * HH + 2 * kk + 1]);
    }
    if (tid < NG) s_wih2[tid] = pack2(w_ih[tid * 2], w_ih[tid * 2 + 1]);
    if (tid < 32) s_brz[tid] = b_ih[tid] + b_hh[tid];
    if (tid < 16) { s_bin[tid] = b_ih[32 + tid]; s_bhn[tid] = b_hh[32 + tid]; }
    if (tid < KP) {
        s_ws2[tid] = pack2(w_sum[2 * tid], w_sum[2 * tid + 1]);
        s_wc2[tid] = pack2(w_carry[2 * tid], w_carry[2 * tid + 1]);
    }
    if (tid == 0) { s_bs = b_sum[0]; s_bc = b_carry[0]; }
    __syncthreads();

    const int e = blockIdx.x * THREADS + tid;

    const float4* xp4 = reinterpret_cast<const float4*>(x + (size_t)e * (TT * 2));
    float4 x0 = xp4[0], x1 = xp4[1];
    u64 xp[TT] = { pack2(x0.x, x0.y), pack2(x0.z, x0.w),
                   pack2(x1.x, x1.y), pack2(x1.z, x1.w) };

    u64 h2[KP];
#pragma unroll
    for (int kk = 0; kk < KP; ++kk) h2[kk] = 0ull;

#pragma unroll
    for (int t = 0; t < TT; ++t) {
        const u64 xt = xp[t];
        const bool hh_on = (t != 0);   // compile-time per unrolled copy

        // ----- gate loop: intentionally NOT unrolled (keeps regs bounded) -----
#pragma unroll 1
        for (int j = 0; j < HH; ++j) {
            float gr, gz, n_pre;
            if (hh_on) {
                u64 ar = pack2(s_brz[j], 0.0f);
                u64 az = pack2(s_brz[16 + j], 0.0f);
                u64 an = pack2(s_bhn[j], 0.0f);
                ffma2(ar, s_wih2[j], xt);
                ffma2(az, s_wih2[16 + j], xt);
                const u64* wr = s_whh2[j];
                const u64* wz = s_whh2[16 + j];
                const u64* wn = s_whh2[32 + j];
#pragma unroll
                for (int kk = 0; kk < KP; ++kk) {
                    ffma2(ar, wr[kk], h2[kk]);
                    ffma2(az, wz[kk], h2[kk]);
                    ffma2(an, wn[kk], h2[kk]);
                }
                gr = hsum2(ar);
                gz = hsum2(az);
                float nh = hsum2(an);
                u64 ai = pack2(s_bin[j], 0.0f);
                ffma2(ai, s_wih2[32 + j], xt);
                float r = sigmoid_f(gr);
                n_pre = hsum2(ai) + r * nh;
            } else {
                u64 ar = pack2(s_brz[j], 0.0f);
                u64 az = pack2(s_brz[16 + j], 0.0f);
                u64 ai = pack2(s_bin[j], 0.0f);
                ffma2(ar, s_wih2[j], xt);
                ffma2(az, s_wih2[16 + j], xt);
                ffma2(ai, s_wih2[32 + j], xt);
                gr = hsum2(ar);
                gz = hsum2(az);
                float r = sigmoid_f(gr);
                n_pre = hsum2(ai) + r * s_bhn[j];
            }
            float z = sigmoid_f(gz);
            float n = tanh_f(n_pre);
            float2 hop = unpack2(h2[j >> 1]);
            float ho = (j & 1) ? hop.y : hop.x;
            s_hn[j][tid] = n + z * (ho - n);   // stage new h (thread-private column)
        }

        // commit: read staged new h back (conflict-free, static indices)
#pragma unroll
        for (int kk = 0; kk < KP; ++kk)
            h2[kk] = pack2(s_hn[2 * kk][tid], s_hn[2 * kk + 1][tid]);

        // sum logit
        u64 sa = pack2(s_bs, 0.0f);
#pragma unroll
        for (int kk = 0; kk < KP; ++kk) ffma2(sa, s_ws2[kk], h2[kk]);
        float sO = hsum2(sa);

        if (off_hid >= 0) {
            float4* po = reinterpret_cast<float4*>(out + off_hid + ((size_t)e * TT + t) * HH);
#pragma unroll
            for (int q = 0; q < 4; ++q) {
                float2 a0 = unpack2(h2[2 * q]), a1 = unpack2(h2[2 * q + 1]);
                po[q] = make_float4(a0.x, a0.y, a1.x, a1.y);
            }
        }
        if (off_sum >= 0) out[off_sum + (size_t)e * TT + t] = sO;
        if (off_log >= 0) out[off_log + (size_t)e * (TT + 1) + t] = sO;
    }

    u64 ca = pack2(s_bc, 0.0f);
#pragma unroll
    for (int kk = 0; kk < KP; ++kk) ffma2(ca, s_wc2[kk], h2[kk]);
    float cO = hsum2(ca);
    if (off_car >= 0) out[off_car + e] = cO;
    if (off_log >= 0) out[off_log + (size_t)e * (TT + 1) + TT] = cO;
}

extern "C" void kernel_launch(void* const* d_in, const int* in_sizes, int n_in,
                              void* d_out, int out_size)
{
    const float* x       = (const float*)d_in[0];
    const float* w_ih    = (const float*)d_in[1];
    const float* w_hh    = (const float*)d_in[2];
    const float* b_ih    = (const float*)d_in[3];
    const float* b_hh    = (const float*)d_in[4];
    const float* w_sum   = (const float*)d_in[5];
    const float* b_sum   = (const float*)d_in[6];
    const float* w_carry = (const float*)d_in[7];
    const float* b_carry = (const float*)d_in[8];
    float* out = (float*)d_out;

    const long long HID = 0;
    const long long SUM = (long long)BATCH * TT * HH;          // 67108864
    const long long CAR = SUM + (long long)BATCH * TT;         // 71303168
    const long long LOG = CAR + (long long)BATCH;              // 72351744
    const long long FULL = LOG + (long long)BATCH * (TT + 1);  // 77594624

    long long oh = -1, os = -1, oc = -1, ol = -1;
    long long sz = (long long)out_size;
    if (sz == FULL)                               { oh = HID; os = SUM; oc = CAR; ol = LOG; }
    else if (sz == (long long)BATCH * TT * HH)    { oh = 0; }
    else if (sz == (long long)BATCH * (TT + 1))   { ol = 0; }
    else if (sz == (long long)BATCH * TT)         { os = 0; }
    else if (sz == (long long)BATCH)              { oc = 0; }
    else                                          { oh = HID; os = SUM; oc = CAR; ol = LOG; }

    const int blocks = BATCH / THREADS;   // 8192
    gru_adder_kernel<<<blocks, THREADS>>>(x, w_ih, w_hh, b_ih, b_hh,
                                          w_sum, b_sum, w_carry, b_carry,
                                          out, oh, os, oc, ol);
}

// round 6
// speedup vs baseline: 7.2046x; 1.1747x over previous
#include <cuda_runtime.h>

// GRUAdder: B=1048576, T=4, I=2, H=16
// out = concat(hidden_table[B,4,16], sum_logits[B,4], carry[B,1], output_logits[B,5]) fp32

static constexpr int BATCH   = 1048576;
static constexpr int TT      = 4;
static constexpr int HH      = 16;
static constexpr int NG      = 48;   // 3*H gate rows
static constexpr int KP      = 8;    // H/2 k-pairs
static constexpr int THREADS = 128;
static constexpr int ELEMS   = 2;

typedef unsigned long long u64;

__device__ __forceinline__ u64 pack2(float lo, float hi) {
    u64 r; asm("mov.b64 %0, {%1, %2};" : "=l"(r) : "f"(lo), "f"(hi)); return r;
}
__device__ __forceinline__ float2 unpack2(u64 v) {
    float2 f; asm("mov.b64 {%0, %1}, %2;" : "=f"(f.x), "=f"(f.y) : "l"(v)); return f;
}
__device__ __forceinline__ void ffma2(u64 &d, u64 a, u64 b) {
    asm("fma.rn.f32x2 %0, %1, %2, %0;" : "+l"(d) : "l"(a), "l"(b));
}
__device__ __forceinline__ float hsum2(u64 v) { float2 f = unpack2(v); return f.x + f.y; }
__device__ __forceinline__ float sigmoid_f(float x) {
    return __fdividef(1.0f, 1.0f + __expf(-x));
}
__device__ __forceinline__ float tanh_f(float x) {
    float e = __expf(2.0f * x);
    return __fdividef(e - 1.0f, e + 1.0f);
}

__global__ void __launch_bounds__(THREADS, 4)
gru_adder_kernel(const float* __restrict__ x,       // [B,4,2]
                 const float* __restrict__ w_ih,    // [48,2]
                 const float* __restrict__ w_hh,    // [48,16]
                 const float* __restrict__ b_ih,    // [48]
                 const float* __restrict__ b_hh,    // [48]
                 const float* __restrict__ w_sum,   // [16]
                 const float* __restrict__ b_sum,   // [1]
                 const float* __restrict__ w_carry, // [16]
                 const float* __restrict__ b_carry, // [1]
                 float* __restrict__ out,
                 long long off_hid, long long off_sum,
                 long long off_car, long long off_log)
{
    __shared__ __align__(16) u64 s_whh2[NG][KP]; // {w_hh[g][2k], w_hh[g][2k+1]}
    __shared__ u64   s_wih2[NG];       // {w_ih[g][0], w_ih[g][1]}
    __shared__ float s_brz[32];        // b_ih + b_hh for r,z gates
    __shared__ float s_bin[16];        // b_ih[32+j]
    __shared__ float s_bhn[16];        // b_hh[32+j]
    __shared__ u64   s_ws2[KP], s_wc2[KP];
    __shared__ float s_bs, s_bc;
    __shared__ float s_hnA[HH][THREADS];  // new-h staging, element A
    __shared__ float s_hnB[HH][THREADS];  // new-h staging, element B

    const int tid = threadIdx.x;
    for (int i = tid; i < NG * KP; i += THREADS) {
        int g = i / KP, kk = i % KP;
        s_whh2[g][kk] = pack2(w_hh[g * HH + 2 * kk], w_hh[g * HH + 2 * kk + 1]);
    }
    if (tid < NG) s_wih2[tid] = pack2(w_ih[tid * 2], w_ih[tid * 2 + 1]);
    if (tid < 32) s_brz[tid] = b_ih[tid] + b_hh[tid];
    if (tid < 16) { s_bin[tid] = b_ih[32 + tid]; s_bhn[tid] = b_hh[32 + tid]; }
    if (tid < KP) {
        s_ws2[tid] = pack2(w_sum[2 * tid], w_sum[2 * tid + 1]);
        s_wc2[tid] = pack2(w_carry[2 * tid], w_carry[2 * tid + 1]);
    }
    if (tid == 0) { s_bs = b_sum[0]; s_bc = b_carry[0]; }
    __syncthreads();

    const int base = blockIdx.x * (THREADS * ELEMS) + tid;
    const int eA = base;
    const int eB = base + THREADS;

    const float4* xpA4 = reinterpret_cast<const float4*>(x + (size_t)eA * (TT * 2));
    const float4* xpB4 = reinterpret_cast<const float4*>(x + (size_t)eB * (TT * 2));
    float4 xA0 = xpA4[0], xA1 = xpA4[1];
    float4 xB0 = xpB4[0], xB1 = xpB4[1];
    u64 xpA[TT] = { pack2(xA0.x, xA0.y), pack2(xA0.z, xA0.w),
                    pack2(xA1.x, xA1.y), pack2(xA1.z, xA1.w) };
    u64 xpB[TT] = { pack2(xB0.x, xB0.y), pack2(xB0.z, xB0.w),
                    pack2(xB1.x, xB1.y), pack2(xB1.z, xB1.w) };

    u64 h2A[KP], h2B[KP];
#pragma unroll
    for (int kk = 0; kk < KP; ++kk) { h2A[kk] = 0ull; h2B[kk] = 0ull; }

#pragma unroll
    for (int t = 0; t < TT; ++t) {
        const u64 xtA = xpA[t], xtB = xpB[t];
        const bool hh_on = (t != 0);   // compile-time per unrolled copy

        // ----- rolled gate loop (keeps registers bounded) -----
#pragma unroll 1
        for (int j = 0; j < HH; ++j) {
            const u64 wr0 = s_wih2[j], wz0 = s_wih2[16 + j], wn0 = s_wih2[32 + j];
            const float brj = s_brz[j], bzj = s_brz[16 + j];
            const float binj = s_bin[j], bhnj = s_bhn[j];

            float grA, grB, gzA, gzB, npA, npB;
            if (hh_on) {
                u64 arA = pack2(brj, 0.0f), arB = arA;
                u64 azA = pack2(bzj, 0.0f), azB = azA;
                u64 anA = pack2(bhnj, 0.0f), anB = anA;
                ffma2(arA, wr0, xtA); ffma2(arB, wr0, xtB);
                ffma2(azA, wz0, xtA); ffma2(azB, wz0, xtB);
                const ulonglong2* wr = reinterpret_cast<const ulonglong2*>(s_whh2[j]);
                const ulonglong2* wz = reinterpret_cast<const ulonglong2*>(s_whh2[16 + j]);
                const ulonglong2* wn = reinterpret_cast<const ulonglong2*>(s_whh2[32 + j]);
#pragma unroll
                for (int q = 0; q < 4; ++q) {
                    ulonglong2 a = wr[q];     // one LDS.128 feeds 4 FFMA2 (both elems)
                    ffma2(arA, a.x, h2A[2 * q]); ffma2(arA, a.y, h2A[2 * q + 1]);
                    ffma2(arB, a.x, h2B[2 * q]); ffma2(arB, a.y, h2B[2 * q + 1]);
                    ulonglong2 b = wz[q];
                    ffma2(azA, b.x, h2A[2 * q]); ffma2(azA, b.y, h2A[2 * q + 1]);
                    ffma2(azB, b.x, h2B[2 * q]); ffma2(azB, b.y, h2B[2 * q + 1]);
                    ulonglong2 c = wn[q];
                    ffma2(anA, c.x, h2A[2 * q]); ffma2(anA, c.y, h2A[2 * q + 1]);
                    ffma2(anB, c.x, h2B[2 * q]); ffma2(anB, c.y, h2B[2 * q + 1]);
                }
                grA = hsum2(arA); grB = hsum2(arB);
                gzA = hsum2(azA); gzB = hsum2(azB);
                u64 aiA = pack2(binj, 0.0f), aiB = aiA;
                ffma2(aiA, wn0, xtA); ffma2(aiB, wn0, xtB);
                float rA = sigmoid_f(grA), rB = sigmoid_f(grB);
                npA = hsum2(aiA) + rA * hsum2(anA);
                npB = hsum2(aiB) + rB * hsum2(anB);
            } else {
                u64 arA = pack2(brj, 0.0f), arB = arA;
                u64 azA = pack2(bzj, 0.0f), azB = azA;
                u64 aiA = pack2(binj, 0.0f), aiB = aiA;
                ffma2(arA, wr0, xtA); ffma2(arB, wr0, xtB);
                ffma2(azA, wz0, xtA); ffma2(azB, wz0, xtB);
                ffma2(aiA, wn0, xtA); ffma2(aiB, wn0, xtB);
                grA = hsum2(arA); grB = hsum2(arB);
                gzA = hsum2(azA); gzB = hsum2(azB);
                float rA = sigmoid_f(grA), rB = sigmoid_f(grB);
                npA = hsum2(aiA) + rA * bhnj;
                npB = hsum2(aiB) + rB * bhnj;
            }
            float zA = sigmoid_f(gzA), zB = sigmoid_f(gzB);
            float nA = tanh_f(npA),   nB = tanh_f(npB);
            float2 hpA = unpack2(h2A[j >> 1]);
            float2 hpB = unpack2(h2B[j >> 1]);
            float hoA = (j & 1) ? hpA.y : hpA.x;
            float hoB = (j & 1) ? hpB.y : hpB.x;
            s_hnA[j][tid] = nA + zA * (hoA - nA);
            s_hnB[j][tid] = nB + zB * (hoB - nB);
        }

        // commit staged new h (conflict-free, static indices)
#pragma unroll
        for (int kk = 0; kk < KP; ++kk) {
            h2A[kk] = pack2(s_hnA[2 * kk][tid], s_hnA[2 * kk + 1][tid]);
            h2B[kk] = pack2(s_hnB[2 * kk][tid], s_hnB[2 * kk + 1][tid]);
        }

        // sum logits
        u64 sa = pack2(s_bs, 0.0f), sb = pack2(s_bs, 0.0f);
#pragma unroll
        for (int kk = 0; kk < KP; ++kk) {
            u64 w = s_ws2[kk];
            ffma2(sa, w, h2A[kk]);
            ffma2(sb, w, h2B[kk]);
        }
        float sA = hsum2(sa), sB = hsum2(sb);

        if (off_hid >= 0) {
            float4* poA = reinterpret_cast<float4*>(out + off_hid + ((size_t)eA * TT + t) * HH);
            float4* poB = reinterpret_cast<float4*>(out + off_hid + ((size_t)eB * TT + t) * HH);
#pragma unroll
            for (int q = 0; q < 4; ++q) {
                float2 a0 = unpack2(h2A[2 * q]), a1 = unpack2(h2A[2 * q + 1]);
                poA[q] = make_float4(a0.x, a0.y, a1.x, a1.y);
            }
#pragma unroll
            for (int q = 0; q < 4; ++q) {
                float2 b0 = unpack2(h2B[2 * q]), b1 = unpack2(h2B[2 * q + 1]);
                poB[q] = make_float4(b0.x, b0.y, b1.x, b1.y);
            }
        }
        if (off_sum >= 0) {
            out[off_sum + (size_t)eA * TT + t] = sA;
            out[off_sum + (size_t)eB * TT + t] = sB;
        }
        if (off_log >= 0) {
            out[off_log + (size_t)eA * (TT + 1) + t] = sA;
            out[off_log + (size_t)eB * (TT + 1) + t] = sB;
        }
    }

    // carry head
    u64 ca = pack2(s_bc, 0.0f), cb = pack2(s_bc, 0.0f);
#pragma unroll
    for (int kk = 0; kk < KP; ++kk) {
        u64 w = s_wc2[kk];
        ffma2(ca, w, h2A[kk]);
        ffma2(cb, w, h2B[kk]);
    }
    float cA = hsum2(ca), cB = hsum2(cb);
    if (off_car >= 0) { out[off_car + eA] = cA; out[off_car + eB] = cB; }
    if (off_log >= 0) {
        out[off_log + (size_t)eA * (TT + 1) + TT] = cA;
        out[off_log + (size_t)eB * (TT + 1) + TT] = cB;
    }
}

extern "C" void kernel_launch(void* const* d_in, const int* in_sizes, int n_in,
                              void* d_out, int out_size)
{
    const float* x       = (const float*)d_in[0];
    const float* w_ih    = (const float*)d_in[1];
    const float* w_hh    = (const float*)d_in[2];
    const float* b_ih    = (const float*)d_in[3];
    const float* b_hh    = (const float*)d_in[4];
    const float* w_sum   = (const float*)d_in[5];
    const float* b_sum   = (const float*)d_in[6];
    const float* w_carry = (const float*)d_in[7];
    const float* b_carry = (const float*)d_in[8];
    float* out = (float*)d_out;

    const long long HID = 0;
    const long long SUM = (long long)BATCH * TT * HH;          // 67108864
    const long long CAR = SUM + (long long)BATCH * TT;         // 71303168
    const long long LOG = CAR + (long long)BATCH;              // 72351744
    const long long FULL = LOG + (long long)BATCH * (TT + 1);  // 77594624

    long long oh = -1, os = -1, oc = -1, ol = -1;
    long long sz = (long long)out_size;
    if (sz == FULL)                               { oh = HID; os = SUM; oc = CAR; ol = LOG; }
    else if (sz == (long long)BATCH * TT * HH)    { oh = 0; }
    else if (sz == (long long)BATCH * (TT + 1))   { ol = 0; }
    else if (sz == (long long)BATCH * TT)         { os = 0; }
    else if (sz == (long long)BATCH)              { oc = 0; }
    else                                          { oh = HID; os = SUM; oc = CAR; ol = LOG; }

    const int blocks = BATCH / (THREADS * ELEMS);   // 4096
    gru_adder_kernel<<<blocks, THREADS>>>(x, w_ih, w_hh, b_ih, b_hh,
                                          w_sum, b_sum, w_carry, b_carry,
                                          out, oh, os, oc, ol);
}

// round 7
// speedup vs baseline: 7.8890x; 1.0950x over previous
#include <cuda_runtime.h>

// GRUAdder: B=1048576, T=4, I=2, H=16
// out = concat(hidden_table[B,4,16], sum_logits[B,4], carry[B,1], output_logits[B,5]) fp32

static constexpr int BATCH   = 1048576;
static constexpr int TT      = 4;
static constexpr int HH      = 16;
static constexpr int NG      = 48;   // 3*H gate rows
static constexpr int KP      = 8;    // H/2 k-pairs
static constexpr int THREADS = 128;
static constexpr int ELEMS   = 2;

typedef unsigned long long u64;

__device__ __forceinline__ u64 pack2(float lo, float hi) {
    u64 r; asm("mov.b64 %0, {%1, %2};" : "=l"(r) : "f"(lo), "f"(hi)); return r;
}
__device__ __forceinline__ float2 unpack2(u64 v) {
    float2 f; asm("mov.b64 {%0, %1}, %2;" : "=f"(f.x), "=f"(f.y) : "l"(v)); return f;
}
__device__ __forceinline__ void ffma2(u64 &d, u64 a, u64 b) {
    asm("fma.rn.f32x2 %0, %1, %2, %0;" : "+l"(d) : "l"(a), "l"(b));
}
__device__ __forceinline__ float hsum2(u64 v) { float2 f = unpack2(v); return f.x + f.y; }

// HW tanh (1 MUFU). max err ~1e-4, well within 1e-3 budget.
__device__ __forceinline__ float tanh_fast(float x) {
    float y; asm("tanh.approx.f32 %0, %1;" : "=f"(y) : "f"(x)); return y;
}
// sigmoid(x) = 0.5*tanh(x/2) + 0.5  (1 MUFU + 2 fma-pipe ops)
__device__ __forceinline__ float sigmoid_fast(float x) {
    return fmaf(tanh_fast(0.5f * x), 0.5f, 0.5f);
}

__global__ void __launch_bounds__(THREADS, 4)
gru_adder_kernel(const float* __restrict__ x,       // [B,4,2]
                 const float* __restrict__ w_ih,    // [48,2]
                 const float* __restrict__ w_hh,    // [48,16]
                 const float* __restrict__ b_ih,    // [48]
                 const float* __restrict__ b_hh,    // [48]
                 const float* __restrict__ w_sum,   // [16]
                 const float* __restrict__ b_sum,   // [1]
                 const float* __restrict__ w_carry, // [16]
                 const float* __restrict__ b_carry, // [1]
                 float* __restrict__ out,
                 long long off_hid, long long off_sum,
                 long long off_car, long long off_log)
{
    __shared__ __align__(16) u64 s_whh2[NG][KP];    // {w_hh[g][2k], w_hh[g][2k+1]}
    __shared__ __align__(16) ulonglong2 s_wihrz[HH];// { wih2[j], wih2[16+j] }
    __shared__ u64   s_wn[HH];                      // wih2[32+j]
    __shared__ __align__(16) float4 s_bias4[HH];    // {brz[j], brz[16+j], b_ih[32+j], b_hh[32+j]}
    __shared__ u64   s_ws2[KP], s_wc2[KP];
    __shared__ float s_bs, s_bc;
    __shared__ float s_hnA[HH][THREADS];  // new-h staging, element A
    __shared__ float s_hnB[HH][THREADS];  // new-h staging, element B

    const int tid = threadIdx.x;
    for (int i = tid; i < NG * KP; i += THREADS) {
        int g = i / KP, kk = i % KP;
        s_whh2[g][kk] = pack2(w_hh[g * HH + 2 * kk], w_hh[g * HH + 2 * kk + 1]);
    }
    if (tid < HH) {
        ulonglong2 wrz;
        wrz.x = pack2(w_ih[tid * 2],            w_ih[tid * 2 + 1]);
        wrz.y = pack2(w_ih[(16 + tid) * 2],     w_ih[(16 + tid) * 2 + 1]);
        s_wihrz[tid] = wrz;
        s_wn[tid] = pack2(w_ih[(32 + tid) * 2], w_ih[(32 + tid) * 2 + 1]);
        s_bias4[tid] = make_float4(b_ih[tid] + b_hh[tid],
                                   b_ih[16 + tid] + b_hh[16 + tid],
                                   b_ih[32 + tid],
                                   b_hh[32 + tid]);
    }
    if (tid < KP) {
        s_ws2[tid] = pack2(w_sum[2 * tid], w_sum[2 * tid + 1]);
        s_wc2[tid] = pack2(w_carry[2 * tid], w_carry[2 * tid + 1]);
    }
    if (tid == 0) { s_bs = b_sum[0]; s_bc = b_carry[0]; }
    __syncthreads();

    const int base = blockIdx.x * (THREADS * ELEMS) + tid;
    const int eA = base;
    const int eB = base + THREADS;

    const float4* xpA4 = reinterpret_cast<const float4*>(x + (size_t)eA * (TT * 2));
    const float4* xpB4 = reinterpret_cast<const float4*>(x + (size_t)eB * (TT * 2));
    float4 xA0 = xpA4[0], xA1 = xpA4[1];
    float4 xB0 = xpB4[0], xB1 = xpB4[1];
    u64 xpA[TT] = { pack2(xA0.x, xA0.y), pack2(xA0.z, xA0.w),
                    pack2(xA1.x, xA1.y), pack2(xA1.z, xA1.w) };
    u64 xpB[TT] = { pack2(xB0.x, xB0.y), pack2(xB0.z, xB0.w),
                    pack2(xB1.x, xB1.y), pack2(xB1.z, xB1.w) };

    u64 h2A[KP], h2B[KP];
#pragma unroll
    for (int kk = 0; kk < KP; ++kk) { h2A[kk] = 0ull; h2B[kk] = 0ull; }

#pragma unroll
    for (int t = 0; t < TT; ++t) {
        const u64 xtA = xpA[t], xtB = xpB[t];
        const bool hh_on = (t != 0);   // compile-time per unrolled copy

        // ----- rolled gate loop (keeps registers bounded) -----
#pragma unroll 1
        for (int j = 0; j < HH; ++j) {
            const float4 bias = s_bias4[j];        // 1 LDS.128
            const ulonglong2 wrz = s_wihrz[j];     // 1 LDS.128
            const u64 wn0 = s_wn[j];               // 1 LDS.64

            float grA, grB, gzA, gzB, npA, npB;
            if (hh_on) {
                u64 arA = pack2(bias.x, 0.0f), arB = arA;
                u64 azA = pack2(bias.y, 0.0f), azB = azA;
                u64 anA = pack2(bias.w, 0.0f), anB = anA;
                ffma2(arA, wrz.x, xtA); ffma2(arB, wrz.x, xtB);
                ffma2(azA, wrz.y, xtA); ffma2(azB, wrz.y, xtB);
                const ulonglong2* wr = reinterpret_cast<const ulonglong2*>(s_whh2[j]);
                const ulonglong2* wz = reinterpret_cast<const ulonglong2*>(s_whh2[16 + j]);
                const ulonglong2* wnh = reinterpret_cast<const ulonglong2*>(s_whh2[32 + j]);
#pragma unroll
                for (int q = 0; q < 4; ++q) {
                    ulonglong2 a = wr[q];     // one LDS.128 feeds 4 FFMA2 (both elems)
                    ffma2(arA, a.x, h2A[2 * q]); ffma2(arA, a.y, h2A[2 * q + 1]);
                    ffma2(arB, a.x, h2B[2 * q]); ffma2(arB, a.y, h2B[2 * q + 1]);
                    ulonglong2 b = wz[q];
                    ffma2(azA, b.x, h2A[2 * q]); ffma2(azA, b.y, h2A[2 * q + 1]);
                    ffma2(azB, b.x, h2B[2 * q]); ffma2(azB, b.y, h2B[2 * q + 1]);
                    ulonglong2 c = wnh[q];
                    ffma2(anA, c.x, h2A[2 * q]); ffma2(anA, c.y, h2A[2 * q + 1]);
                    ffma2(anB, c.x, h2B[2 * q]); ffma2(anB, c.y, h2B[2 * q + 1]);
                }
                grA = hsum2(arA); grB = hsum2(arB);
                gzA = hsum2(azA); gzB = hsum2(azB);
                u64 aiA = pack2(bias.z, 0.0f), aiB = aiA;
                ffma2(aiA, wn0, xtA); ffma2(aiB, wn0, xtB);
                float rA = sigmoid_fast(grA), rB = sigmoid_fast(grB);
                npA = hsum2(aiA) + rA * hsum2(anA);
                npB = hsum2(aiB) + rB * hsum2(anB);
            } else {
                u64 arA = pack2(bias.x, 0.0f), arB = arA;
                u64 azA = pack2(bias.y, 0.0f), azB = azA;
                u64 aiA = pack2(bias.z, 0.0f), aiB = aiA;
                ffma2(arA, wrz.x, xtA); ffma2(arB, wrz.x, xtB);
                ffma2(azA, wrz.y, xtA); ffma2(azB, wrz.y, xtB);
                ffma2(aiA, wn0, xtA);   ffma2(aiB, wn0, xtB);
                grA = hsum2(arA); grB = hsum2(arB);
                gzA = hsum2(azA); gzB = hsum2(azB);
                float rA = sigmoid_fast(grA), rB = sigmoid_fast(grB);
                npA = hsum2(aiA) + rA * bias.w;
                npB = hsum2(aiB) + rB * bias.w;
            }
            float zA = sigmoid_fast(gzA), zB = sigmoid_fast(gzB);
            float nA = tanh_fast(npA),    nB = tanh_fast(npB);
            float2 hpA = unpack2(h2A[j >> 1]);
            float2 hpB = unpack2(h2B[j >> 1]);
            float hoA = (j & 1) ? hpA.y : hpA.x;
            float hoB = (j & 1) ? hpB.y : hpB.x;
            s_hnA[j][tid] = nA + zA * (hoA - nA);
            s_hnB[j][tid] = nB + zB * (hoB - nB);
        }

        // commit staged new h (conflict-free, static indices)
#pragma unroll
        for (int kk = 0; kk < KP; ++kk) {
            h2A[kk] = pack2(s_hnA[2 * kk][tid], s_hnA[2 * kk + 1][tid]);
            h2B[kk] = pack2(s_hnB[2 * kk][tid], s_hnB[2 * kk + 1][tid]);
        }

        // sum logits
        u64 sa = pack2(s_bs, 0.0f), sb = pack2(s_bs, 0.0f);
#pragma unroll
        for (int kk = 0; kk < KP; ++kk) {
            u64 w = s_ws2[kk];
            ffma2(sa, w, h2A[kk]);
            ffma2(sb, w, h2B[kk]);
        }
        float sA = hsum2(sa), sB = hsum2(sb);

        if (off_hid >= 0) {
            float4* poA = reinterpret_cast<float4*>(out + off_hid + ((size_t)eA * TT + t) * HH);
            float4* poB = reinterpret_cast<float4*>(out + off_hid + ((size_t)eB * TT + t) * HH);
#pragma unroll
            for (int q = 0; q < 4; ++q) {
                float2 a0 = unpack2(h2A[2 * q]), a1 = unpack2(h2A[2 * q + 1]);
                poA[q] = make_float4(a0.x, a0.y, a1.x, a1.y);
            }
#pragma unroll
            for (int q = 0; q < 4; ++q) {
                float2 b0 = unpack2(h2B[2 * q]), b1 = unpack2(h2B[2 * q + 1]);
                poB[q] = make_float4(b0.x, b0.y, b1.x, b1.y);
            }
        }
        if (off_sum >= 0) {
            out[off_sum + (size_t)eA * TT + t] = sA;
            out[off_sum + (size_t)eB * TT + t] = sB;
        }
        if (off_log >= 0) {
            out[off_log + (size_t)eA * (TT + 1) + t] = sA;
            out[off_log + (size_t)eB * (TT + 1) + t] = sB;
        }
    }

    // carry head
    u64 ca = pack2(s_bc, 0.0f), cb = pack2(s_bc, 0.0f);
#pragma unroll
    for (int kk = 0; kk < KP; ++kk) {
        u64 w = s_wc2[kk];
        ffma2(ca, w, h2A[kk]);
        ffma2(cb, w, h2B[kk]);
    }
    float cA = hsum2(ca), cB = hsum2(cb);
    if (off_car >= 0) { out[off_car + eA] = cA; out[off_car + eB] = cB; }
    if (off_log >= 0) {
        out[off_log + (size_t)eA * (TT + 1) + TT] = cA;
        out[off_log + (size_t)eB * (TT + 1) + TT] = cB;
    }
}

extern "C" void kernel_launch(void* const* d_in, const int* in_sizes, int n_in,
                              void* d_out, int out_size)
{
    const float* x       = (const float*)d_in[0];
    const float* w_ih    = (const float*)d_in[1];
    const float* w_hh    = (const float*)d_in[2];
    const float* b_ih    = (const float*)d_in[3];
    const float* b_hh    = (const float*)d_in[4];
    const float* w_sum   = (const float*)d_in[5];
    const float* b_sum   = (const float*)d_in[6];
    const float* w_carry = (const float*)d_in[7];
    const float* b_carry = (const float*)d_in[8];
    float* out = (float*)d_out;

    const long long HID = 0;
    const long long SUM = (long long)BATCH * TT * HH;          // 67108864
    const long long CAR = SUM + (long long)BATCH * TT;         // 71303168
    const long long LOG = CAR + (long long)BATCH;              // 72351744
    const long long FULL = LOG + (long long)BATCH * (TT + 1);  // 77594624

    long long oh = -1, os = -1, oc = -1, ol = -1;
    long long sz = (long long)out_size;
    if (sz == FULL)                               { oh = HID; os = SUM; oc = CAR; ol = LOG; }
    else if (sz == (long long)BATCH * TT * HH)    { oh = 0; }
    else if (sz == (long long)BATCH * (TT + 1))   { ol = 0; }
    else if (sz == (long long)BATCH * TT)         { os = 0; }
    else if (sz == (long long)BATCH)              { oc = 0; }
    else                                          { oh = HID; os = SUM; oc = CAR; ol = LOG; }

    const int blocks = BATCH / (THREADS * ELEMS);   // 4096
    gru_adder_kernel<<<blocks, THREADS>>>(x, w_ih, w_hh, b_ih, b_hh,
                                          w_sum, b_sum, w_carry, b_carry,
                                          out, oh, os, oc, ol);
}